// round 17
// baseline (speedup 1.0000x reference)
#include <cuda_runtime.h>
#include <cuda_bf16.h>
#include <cstdint>

#define BATCH 2
#define NQS   8192
#define NKS   8192
#define DIM   256
#define NROWS (BATCH * NQS)          // 16384 global rows
#define SOFT_C 40.0f
#define QK_KT  4                     // k-tiles (of 256 keys) per qk CTA

typedef __nv_bfloat16 bf16;

// ---------------- device scratch (allocation-free) ----------------
__device__ bf16  g_xh [(size_t)3 * NROWS * DIM];    // split of raw q,k,v [z][row][d]
__device__ bf16  g_xl [(size_t)3 * NROWS * DIM];
__device__ bf16  g_wth[(size_t)3 * DIM * DIM];      // W^T split [z][n][k]
__device__ bf16  g_wtl[(size_t)3 * DIM * DIM];
__device__ bf16  g_qh [(size_t)NROWS * DIM];        // Q emb hi/lo [row][d]
__device__ bf16  g_ql [(size_t)NROWS * DIM];
__device__ bf16  g_kh [(size_t)NROWS * DIM];
__device__ bf16  g_kl [(size_t)NROWS * DIM];
__device__ bf16  g_vth[(size_t)BATCH * DIM * NKS];  // V^T hi/lo [b][d][n]
__device__ bf16  g_vtl[(size_t)BATCH * DIM * NKS];
__device__ bf16  g_ph [(size_t)BATCH * NQS * NKS];  // exp(S-C) hi/lo
__device__ bf16  g_pl [(size_t)BATCH * NQS * NKS];
__device__ float g_lpart[(size_t)BATCH * NQS * 128];
__device__ float g_linv[(size_t)BATCH * NQS];

__device__ __forceinline__ uint32_t smem_u32(const void* p) {
    uint32_t a;
    asm("{ .reg .u64 t; cvta.to.shared.u64 t, %1; cvt.u32.u64 %0, t; }"
        : "=r"(a) : "l"(p));
    return a;
}
#define LDSM_X4(r0, r1, r2, r3, addr) \
    asm volatile("ldmatrix.sync.aligned.m8n8.x4.shared.b16 {%0,%1,%2,%3}, [%4];" \
                 : "=r"(r0), "=r"(r1), "=r"(r2), "=r"(r3) : "r"(addr))
#define MMA16816(c, a, b) \
    asm volatile("mma.sync.aligned.m16n8k16.row.col.f32.bf16.bf16.f32 " \
                 "{%0,%1,%2,%3}, {%4,%5,%6,%7}, {%8,%9}, {%0,%1,%2,%3};" \
                 : "+f"((c)[0]), "+f"((c)[1]), "+f"((c)[2]), "+f"((c)[3]) \
                 : "r"((a)[0]), "r"((a)[1]), "r"((a)[2]), "r"((a)[3]),    \
                   "r"((b)[0]), "r"((b)[1]))
#define CP_ASYNC16(saddr, gptr) \
    asm volatile("cp.async.cg.shared.global [%0], [%1], 16;" \
                 :: "r"(saddr), "l"(__cvta_generic_to_global(gptr)) : "memory")
#define CP_COMMIT() asm volatile("cp.async.commit_group;" ::: "memory")
#define CP_WAIT(n)  asm volatile("cp.async.wait_group %0;" :: "n"(n) : "memory")

__device__ __forceinline__ uint32_t swoff(int row, int colb) {
    uint32_t rb = (uint32_t)row * 128u;
    return rb + ((uint32_t)colb ^ ((rb >> 3) & 0x70u));
}
__device__ __forceinline__ uint32_t pack2(bf16 a, bf16 b) {
    return (uint32_t)__bfloat16_as_ushort(a) | ((uint32_t)__bfloat16_as_ushort(b) << 16);
}
__device__ __forceinline__ void split1(float f, bf16& h, bf16& l) {
    h = __float2bfloat16(f);
    l = __float2bfloat16(f - __bfloat162float(h));
}

// ---------------------------------------------------------------------------
// Split raw inputs x (q,k,v) into bf16 hi/lo planes. grid (4096, 3) x 256.
// ---------------------------------------------------------------------------
__global__ __launch_bounds__(256) void split_kernel(
    const float* __restrict__ q, const float* __restrict__ k, const float* __restrict__ v)
{
    const int z = blockIdx.y;
    const float* src = (z == 0) ? q : (z == 1) ? k : v;
    size_t i4 = (size_t)blockIdx.x * 256 + threadIdx.x;      // float4 index
    float4 f = *(const float4*)(src + i4 * 4);
    bf16 h[4], l[4];
    split1(f.x, h[0], l[0]); split1(f.y, h[1], l[1]);
    split1(f.z, h[2], l[2]); split1(f.w, h[3], l[3]);
    size_t off = (size_t)z * NROWS * DIM + i4 * 4;
    uint2 uh; uh.x = pack2(h[0], h[1]); uh.y = pack2(h[2], h[3]);
    uint2 ul; ul.x = pack2(l[0], l[1]); ul.y = pack2(l[2], l[3]);
    *(uint2*)(g_xh + off) = uh;
    *(uint2*)(g_xl + off) = ul;
}

// Transpose + split W into W^T hi/lo. grid (64, 3) x 256.
__global__ __launch_bounds__(256) void wsplit_kernel(
    const float* __restrict__ Wq, const float* __restrict__ Wk, const float* __restrict__ Wv)
{
    const int z = blockIdx.y;
    const float* W = (z == 0) ? Wq : (z == 1) ? Wk : Wv;
    int idx = blockIdx.x * 256 + threadIdx.x;    // 0..65535
    int kk = idx >> 8, nn = idx & 255;
    bf16 h, l;
    split1(W[(size_t)kk * DIM + nn], h, l);
    size_t o = (size_t)z * DIM * DIM + (size_t)nn * DIM + kk;
    g_wth[o] = h;
    g_wtl[o] = l;
}

// Async-stage a [ROWS rows][64 bf16] tile into SW128 SMEM (512 threads).
template <int ROWS>
__device__ __forceinline__ void stage_async(uint32_t sdst, const bf16* __restrict__ src,
                                            size_t stride, int tid)
{
    constexpr int GRANULES = ROWS * 8;
    #pragma unroll
    for (int i = 0; i < GRANULES / 512; i++) {
        int idx = tid + i * 512;
        int r   = idx >> 3;
        int c16 = idx & 7;
        CP_ASYNC16(sdst + swoff(r, c16 * 16),
                   src + (size_t)r * stride + c16 * 8);
    }
}

// Stage all 4 tiles of one K=64 chunk: A[128] hi/lo + B[256] hi/lo = 96 KB.
__device__ __forceinline__ void stage_chunk(
    uint32_t s, const bf16* ah, const bf16* al, size_t astr,
    const bf16* bh, const bf16* bl, size_t bstr, int tid)
{
    stage_async<128>(s,          ah, astr, tid);
    stage_async<128>(s + 16384,  al, astr, tid);
    stage_async<256>(s + 32768,  bh, bstr, tid);
    stage_async<256>(s + 65536,  bl, bstr, tid);
    CP_COMMIT();
}

// One K=64 chunk of the split-3 bf16 GEMM. Warp tile 32(m) x 64(n), 16 warps.
__device__ __forceinline__ void gemm_chunk(
    uint32_t s, int lane, int warp_m, int warp_n, float acc[2][8][4])
{
    const uint32_t sAh = s, sAl = s + 16384, sBh = s + 32768, sBl = s + 65536;
    const int arow0 = warp_m * 32 + (lane & 15);
    const int acol0 = ((lane >> 4) & 1) * 16;
    const int brow0 = warp_n * 64 + (lane & 7) + ((lane >> 4) & 1) * 8;
    const int bcol0 = ((lane >> 3) & 1) * 16;

    #pragma unroll
    for (int ks = 0; ks < 4; ks++) {
        uint32_t ah[2][4], al[2][4];
        #pragma unroll
        for (int mi = 0; mi < 2; mi++) {
            LDSM_X4(ah[mi][0], ah[mi][1], ah[mi][2], ah[mi][3],
                    sAh + swoff(arow0 + mi * 16, ks * 32 + acol0));
            LDSM_X4(al[mi][0], al[mi][1], al[mi][2], al[mi][3],
                    sAl + swoff(arow0 + mi * 16, ks * 32 + acol0));
        }
        #pragma unroll
        for (int nh = 0; nh < 2; nh++) {
            uint32_t bh[4][2], bl[4][2];
            #pragma unroll
            for (int np = 0; np < 2; np++) {
                LDSM_X4(bh[np*2][0], bh[np*2][1], bh[np*2+1][0], bh[np*2+1][1],
                        sBh + swoff(brow0 + nh * 32 + np * 16, ks * 32 + bcol0));
                LDSM_X4(bl[np*2][0], bl[np*2][1], bl[np*2+1][0], bl[np*2+1][1],
                        sBl + swoff(brow0 + nh * 32 + np * 16, ks * 32 + bcol0));
            }
            #pragma unroll
            for (int mi = 0; mi < 2; mi++)
                #pragma unroll
                for (int f = 0; f < 4; f++) {
                    float* c = acc[mi][nh * 4 + f];
                    MMA16816(c, ah[mi], bh[f]);
                    MMA16816(c, ah[mi], bl[f]);
                    MMA16816(c, al[mi], bh[f]);
                }
        }
    }
}

#define STAGE_BYTES 98304
#define GEMM_SMEM   (2 * STAGE_BYTES + 1024)

#define ACC_INIT(acc) \
    _Pragma("unroll") \
    for (int mi = 0; mi < 2; mi++) \
        _Pragma("unroll") \
        for (int ni = 0; ni < 8; ni++) \
            _Pragma("unroll") \
            for (int j = 0; j < 4; j++) acc[mi][ni][j] = 0.f;

// ---------------------------------------------------------------------------
// proj_mma: emb = x @ W + b, tiles 128 rows x 256 cols, 4 K-chunks, pipelined.
// grid (128 row-tiles, 3 z). z=0 Q, z=1 K (natural); z=2 V^T via SMEM transpose.
// ---------------------------------------------------------------------------
__global__ __launch_bounds__(512, 1) void proj_mma_kernel(
    const float* __restrict__ bq, const float* __restrict__ bk, const float* __restrict__ bv)
{
    extern __shared__ char dyn[];
    char* base = (char*)((((uintptr_t)dyn) + 1023) & ~(uintptr_t)1023);
    uint32_t sb[2];
    sb[0] = smem_u32(base);
    sb[1] = sb[0] + STAGE_BYTES;

    const int tid = threadIdx.x;
    const int lane = tid & 31, wid = tid >> 5;
    const int warp_m = wid & 3, warp_n = wid >> 2;
    const int gid = lane >> 2, tig = lane & 3;
    const int rowBase = blockIdx.x * 128;
    const int z = blockIdx.y;
    const float* bias = (z == 0) ? bq : (z == 1) ? bk : bv;

    const bf16* xh = g_xh + (size_t)z * NROWS * DIM + (size_t)rowBase * DIM;
    const bf16* xl = g_xl + (size_t)z * NROWS * DIM + (size_t)rowBase * DIM;
    const bf16* wh = g_wth + (size_t)z * DIM * DIM;
    const bf16* wl = g_wtl + (size_t)z * DIM * DIM;

    float acc[2][8][4];
    ACC_INIT(acc);

    stage_chunk(sb[0], xh, xl, DIM, wh, wl, DIM, tid);
    for (int kc = 0; kc < 4; kc++) {
        if (kc + 1 < 4) {
            stage_chunk(sb[(kc + 1) & 1], xh + (kc + 1) * 64, xl + (kc + 1) * 64, DIM,
                        wh + (kc + 1) * 64, wl + (kc + 1) * 64, DIM, tid);
            CP_WAIT(1);
        } else {
            CP_WAIT(0);
        }
        __syncthreads();
        gemm_chunk(sb[kc & 1], lane, warp_m, warp_n, acc);
        __syncthreads();
    }

    if (z < 2) {
        bf16* oh = (z == 0) ? g_qh : g_kh;
        bf16* ol = (z == 0) ? g_ql : g_kl;
        #pragma unroll
        for (int mi = 0; mi < 2; mi++)
            #pragma unroll
            for (int rh = 0; rh < 2; rh++) {
                const int row = rowBase + warp_m * 32 + mi * 16 + gid + rh * 8;
                #pragma unroll
                for (int ni = 0; ni < 8; ni++) {
                    int col = warp_n * 64 + ni * 8 + tig * 2;
                    float f0 = acc[mi][ni][rh * 2 + 0] + bias[col];
                    float f1 = acc[mi][ni][rh * 2 + 1] + bias[col + 1];
                    bf16 h0, l0, h1, l1;
                    split1(f0, h0, l0); split1(f1, h1, l1);
                    *(uint32_t*)(oh + (size_t)row * DIM + col) = pack2(h0, h1);
                    *(uint32_t*)(ol + (size_t)row * DIM + col) = pack2(l0, l1);
                }
            }
    } else {
        // V: route through SMEM (stride 257 floats) then store transposed hi/lo.
        float* Sm = (float*)base;    // 128 x 257 floats = 131.6 KB < 192 KB
        #pragma unroll
        for (int mi = 0; mi < 2; mi++)
            #pragma unroll
            for (int rh = 0; rh < 2; rh++) {
                const int n_local = warp_m * 32 + mi * 16 + gid + rh * 8;
                #pragma unroll
                for (int ni = 0; ni < 8; ni++) {
                    int col = warp_n * 64 + ni * 8 + tig * 2;
                    Sm[n_local * 257 + col]     = acc[mi][ni][rh * 2 + 0] + bias[col];
                    Sm[n_local * 257 + col + 1] = acc[mi][ni][rh * 2 + 1] + bias[col + 1];
                }
            }
        __syncthreads();
        const int b  = rowBase >> 13;
        const int n0 = rowBase & (NQS - 1);
        for (int u = tid; u < 256 * 16; u += 512) {
            int d  = u >> 4;
            int n8 = (u & 15) * 8;
            bf16 h[8], l[8];
            #pragma unroll
            for (int j = 0; j < 8; j++)
                split1(Sm[(n8 + j) * 257 + d], h[j], l[j]);
            uint4 uh, ul;
            uh.x = pack2(h[0], h[1]); uh.y = pack2(h[2], h[3]);
            uh.z = pack2(h[4], h[5]); uh.w = pack2(h[6], h[7]);
            ul.x = pack2(l[0], l[1]); ul.y = pack2(l[2], l[3]);
            ul.z = pack2(l[4], l[5]); ul.w = pack2(l[6], l[7]);
            size_t o = ((size_t)b * DIM + d) * NKS + n0 + n8;
            *(uint4*)(g_vth + o) = uh;
            *(uint4*)(g_vtl + o) = ul;
        }
    }
}

// ---------------------------------------------------------------------------
// QK: each CTA computes S[128q x 256k] for QK_KT consecutive k-tiles as ONE
// continuous 16-chunk pipeline (chunk c: kt = c>>2, dc = c&3). Per-kt epilogue
// exp(S-C) -> P hi/lo + deterministic partials at slot kt_global*4 + warp_n.
// grid (64 q-tiles, 32/QK_KT kt-groups, 2 batch).
// ---------------------------------------------------------------------------
__global__ __launch_bounds__(512, 1) void qk_kernel()
{
    extern __shared__ char dyn[];
    char* base = (char*)((((uintptr_t)dyn) + 1023) & ~(uintptr_t)1023);
    uint32_t sb[2];
    sb[0] = smem_u32(base);
    sb[1] = sb[0] + STAGE_BYTES;

    const int tid = threadIdx.x;
    const int lane = tid & 31, wid = tid >> 5;
    const int warp_m = wid & 3, warp_n = wid >> 2;
    const int gid = lane >> 2, tig = lane & 3;
    const int qt = blockIdx.x, ktg = blockIdx.y, b = blockIdx.z;

    const bf16* qh = g_qh + (size_t)(b * NQS + qt * 128) * DIM;
    const bf16* ql = g_ql + (size_t)(b * NQS + qt * 128) * DIM;
    const bf16* kh0 = g_kh + (size_t)(b * NQS + ktg * QK_KT * 256) * DIM;
    const bf16* kl0 = g_kl + (size_t)(b * NQS + ktg * QK_KT * 256) * DIM;

    constexpr int NCH = QK_KT * 4;

    float acc[2][8][4];
    ACC_INIT(acc);

    // chunk c: A = Q d-chunk (c&3); B = K tile (c>>2), d-chunk (c&3)
    stage_chunk(sb[0], qh, ql, DIM, kh0, kl0, DIM, tid);
    for (int c = 0; c < NCH; c++) {
        if (c + 1 < NCH) {
            int dc1 = (c + 1) & 3, kt1 = (c + 1) >> 2;
            stage_chunk(sb[(c + 1) & 1],
                        qh + dc1 * 64, ql + dc1 * 64, DIM,
                        kh0 + (size_t)kt1 * 256 * DIM + dc1 * 64,
                        kl0 + (size_t)kt1 * 256 * DIM + dc1 * 64, DIM, tid);
            CP_WAIT(1);
        } else {
            CP_WAIT(0);
        }
        __syncthreads();
        gemm_chunk(sb[c & 1], lane, warp_m, warp_n, acc);
        __syncthreads();

        if ((c & 3) == 3) {
            // epilogue for k-tile kt (256 keys); overlaps already-issued prefetch
            const int kt_global = ktg * QK_KT + (c >> 2);
            #pragma unroll
            for (int mi = 0; mi < 2; mi++)
                #pragma unroll
                for (int rh = 0; rh < 2; rh++) {
                    const int qrow = qt * 128 + warp_m * 32 + mi * 16 + gid + rh * 8;
                    bf16* ph = g_ph + (size_t)(b * NQS + qrow) * NKS + kt_global * 256;
                    bf16* pl = g_pl + (size_t)(b * NQS + qrow) * NKS + kt_global * 256;
                    float rsum = 0.f;
                    #pragma unroll
                    for (int ni = 0; ni < 8; ni++) {
                        float p0 = __expf(acc[mi][ni][rh * 2 + 0] - SOFT_C);
                        float p1 = __expf(acc[mi][ni][rh * 2 + 1] - SOFT_C);
                        rsum += p0 + p1;
                        bf16 h0, l0, h1, l1;
                        split1(p0, h0, l0); split1(p1, h1, l1);
                        int col = warp_n * 64 + ni * 8 + tig * 2;
                        *(uint32_t*)(ph + col) = pack2(h0, h1);
                        *(uint32_t*)(pl + col) = pack2(l0, l1);
                        acc[mi][ni][rh * 2 + 0] = 0.f;
                        acc[mi][ni][rh * 2 + 1] = 0.f;
                    }
                    rsum += __shfl_xor_sync(0xffffffffu, rsum, 1);
                    rsum += __shfl_xor_sync(0xffffffffu, rsum, 2);
                    if (tig == 0)
                        g_lpart[(size_t)(b * NQS + qrow) * 128 + kt_global * 4 + warp_n] = rsum;
                }
        }
    }
}

// ---------------------------------------------------------------------------
__global__ void lred_kernel()
{
    int r = blockIdx.x * 256 + threadIdx.x;
    if (r < BATCH * NQS) {
        const float* p = g_lpart + (size_t)r * 128;
        float s = 0.f;
        #pragma unroll 8
        for (int i = 0; i < 128; i++) s += p[i];
        g_linv[r] = 1.f / s;
    }
}

// ---------------------------------------------------------------------------
// PV: O[128q x 256d] = P V (split-3) over 128 key-chunks, pipelined.
// grid (64 q-tiles, 2 batch).
// ---------------------------------------------------------------------------
__global__ __launch_bounds__(512, 1) void pv_kernel(float* __restrict__ out)
{
    extern __shared__ char dyn[];
    char* base = (char*)((((uintptr_t)dyn) + 1023) & ~(uintptr_t)1023);
    uint32_t sb[2];
    sb[0] = smem_u32(base);
    sb[1] = sb[0] + STAGE_BYTES;

    const int tid = threadIdx.x;
    const int lane = tid & 31, wid = tid >> 5;
    const int warp_m = wid & 3, warp_n = wid >> 2;
    const int gid = lane >> 2, tig = lane & 3;
    const int qt = blockIdx.x, b = blockIdx.y;

    const bf16* ph = g_ph + (size_t)(b * NQS + qt * 128) * NKS;
    const bf16* pl = g_pl + (size_t)(b * NQS + qt * 128) * NKS;
    const bf16* vh = g_vth + (size_t)b * DIM * NKS;
    const bf16* vl = g_vtl + (size_t)b * DIM * NKS;

    float acc[2][8][4];
    ACC_INIT(acc);

    stage_chunk(sb[0], ph, pl, NKS, vh, vl, NKS, tid);
    for (int kc = 0; kc < NKS / 64; kc++) {
        if (kc + 1 < NKS / 64) {
            stage_chunk(sb[(kc + 1) & 1], ph + (kc + 1) * 64, pl + (kc + 1) * 64, NKS,
                        vh + (kc + 1) * 64, vl + (kc + 1) * 64, NKS, tid);
            CP_WAIT(1);
        } else {
            CP_WAIT(0);
        }
        __syncthreads();
        gemm_chunk(sb[kc & 1], lane, warp_m, warp_n, acc);
        __syncthreads();
    }

    #pragma unroll
    for (int mi = 0; mi < 2; mi++)
        #pragma unroll
        for (int rh = 0; rh < 2; rh++) {
            const int qrow = qt * 128 + warp_m * 32 + mi * 16 + gid + rh * 8;
            const float linv = g_linv[b * NQS + qrow];
            float* op = out + (size_t)(b * NQS + qrow) * DIM;
            #pragma unroll
            for (int ni = 0; ni < 8; ni++) {
                int col = warp_n * 64 + ni * 8 + tig * 2;
                float2 o;
                o.x = acc[mi][ni][rh * 2 + 0] * linv;
                o.y = acc[mi][ni][rh * 2 + 1] * linv;
                *(float2*)(op + col) = o;
            }
        }
}

// ---------------------------------------------------------------------------
extern "C" void kernel_launch(void* const* d_in, const int* in_sizes, int n_in,
                              void* d_out, int out_size)
{
    (void)in_sizes; (void)n_in; (void)out_size;
    const float* q  = (const float*)d_in[0];
    const float* k  = (const float*)d_in[1];
    const float* v  = (const float*)d_in[2];
    const float* Wq = (const float*)d_in[3];
    const float* bq = (const float*)d_in[4];
    const float* Wk = (const float*)d_in[5];
    const float* bk = (const float*)d_in[6];
    const float* Wv = (const float*)d_in[7];
    const float* bv = (const float*)d_in[8];
    float* out = (float*)d_out;

    (void)cudaFuncSetAttribute(proj_mma_kernel,
        cudaFuncAttributeMaxDynamicSharedMemorySize, GEMM_SMEM);
    (void)cudaFuncSetAttribute(qk_kernel,
        cudaFuncAttributeMaxDynamicSharedMemorySize, GEMM_SMEM);
    (void)cudaFuncSetAttribute(pv_kernel,
        cudaFuncAttributeMaxDynamicSharedMemorySize, GEMM_SMEM);

    dim3 sg((NROWS * DIM) / (256 * 4), 3);
    split_kernel<<<sg, 256>>>(q, k, v);

    dim3 wg((DIM * DIM) / 256, 3);
    wsplit_kernel<<<wg, 256>>>(Wq, Wk, Wv);

    dim3 pgm(NROWS / 128, 3);
    proj_mma_kernel<<<pgm, 512, GEMM_SMEM>>>(bq, bk, bv);

    dim3 qg(NQS / 128, (NKS / 256) / QK_KT, BATCH);
    qk_kernel<<<qg, 512, GEMM_SMEM>>>();

    lred_kernel<<<(BATCH * NQS + 255) / 256, 256>>>();

    dim3 vg(NQS / 128, BATCH);
    pv_kernel<<<vg, 512, GEMM_SMEM>>>(out);
}